// round 14
// baseline (speedup 1.0000x reference)
#include <cuda_runtime.h>
#include <cuda_fp16.h>
#include <cstdint>

#define N_TOK 4096
#define DIM   1024
#define HID   1024
#define NE    8
#define NSEG  9

// ---------------- scratch ---------------------------------------------------
__device__ int   g_cnt[NSEG];
__device__ int   g_assign_token[NE * N_TOK];
__device__ int   g_assign_slot [NE * N_TOK];
__device__ int   g_top_e[N_TOK * 2];
__device__ float g_top_w[N_TOK * 2];
__device__ __half g_Xf[(size_t)N_TOK * DIM];
// fp16 weights needed only for gemm2: Wd[0..7] -> slots 0..7, sd -> slot 8
__device__ __half g_Wdf[(size_t)9 * DIM * HID];
__device__ __half g_Hf[(size_t)NSEG * N_TOK * HID];
__device__ float g_rbuf[(size_t)3 * N_TOK * DIM];

// ---------------- helpers ---------------------------------------------------
__device__ __forceinline__ uint32_t smem_u32(const void* p) {
    uint32_t a;
    asm("{ .reg .u64 t; cvta.to.shared.u64 t, %1; cvt.u32.u64 %0, t; }"
        : "=r"(a) : "l"(p));
    return a;
}
#define CP_ASYNC16(dst, src) \
    asm volatile("cp.async.cg.shared.global [%0], [%1], 16;" :: "r"(dst), "l"(src))
#define CP_COMMIT() asm volatile("cp.async.commit_group;" ::: "memory")
#define CP_WAIT(n)  asm volatile("cp.async.wait_group %0;" :: "n"(n) : "memory")

__device__ __forceinline__ void ldsm_x4(uint32_t* r, uint32_t addr) {
    asm volatile("ldmatrix.sync.aligned.m8n8.x4.shared.b16 {%0,%1,%2,%3}, [%4];"
        : "=r"(r[0]), "=r"(r[1]), "=r"(r[2]), "=r"(r[3]) : "r"(addr));
}
__device__ __forceinline__ void ldsm_x2_t(uint32_t* r, uint32_t addr) {
    asm volatile("ldmatrix.sync.aligned.m8n8.x2.trans.shared.b16 {%0,%1}, [%2];"
        : "=r"(r[0]), "=r"(r[1]) : "r"(addr));
}
__device__ __forceinline__ void mma_f16(float* d, const uint32_t* a, const uint32_t* b) {
    asm volatile(
        "mma.sync.aligned.m16n8k16.row.col.f32.f16.f16.f32 "
        "{%0,%1,%2,%3}, {%4,%5,%6,%7}, {%8,%9}, {%0,%1,%2,%3};"
        : "+f"(d[0]), "+f"(d[1]), "+f"(d[2]), "+f"(d[3])
        : "r"(a[0]), "r"(a[1]), "r"(a[2]), "r"(a[3]), "r"(b[0]), "r"(b[1]));
}
__device__ __forceinline__ float silu(float g) { return g / (1.f + __expf(-g)); }

__device__ __forceinline__ uint32_t cvt2(float x, float y) {
    __half2 h = __floats2half2_rn(x, y);
    return *(uint32_t*)&h;
}

// ---------------- small kernels ---------------------------------------------
__global__ void zero_kernel() {
    int t = threadIdx.x;
    if (t < NE) g_cnt[t] = 0;
    if (t == NE) g_cnt[NE] = N_TOK;
}

__global__ void convert_x_kernel(const float* __restrict__ x) {
    size_t base = (size_t)blockIdx.x * 1024 + threadIdx.x;
    float4 v[4];
    #pragma unroll
    for (int j = 0; j < 4; j++) v[j] = ((const float4*)x)[base + j * 256];
    #pragma unroll
    for (int j = 0; j < 4; j++)
        ((uint2*)g_Xf)[base + j * 256] =
            make_uint2(cvt2(v[j].x, v[j].y), cvt2(v[j].z, v[j].w));
}

// down matrices (9): Wd[0..7] -> 0..7, sd -> 8
__global__ void convert_w_d_kernel(
    const float* __restrict__ Wd, const float* __restrict__ sd)
{
    int m = blockIdx.y;
    const float* src = (m < 8) ? Wd + (size_t)m * DIM * HID : sd;
    size_t base = (size_t)blockIdx.x * 1024 + threadIdx.x;
    #pragma unroll
    for (int j = 0; j < 4; j++) {
        size_t i4 = base + j * 256;
        float4 v = ((const float4*)src)[i4];
        ((uint2*)g_Wdf)[(size_t)m * (DIM * HID / 4) + i4] =
            make_uint2(cvt2(v.x, v.y), cvt2(v.z, v.w));
    }
}

// router: 1 token per warp, 512 blocks
__global__ __launch_bounds__(256, 4) void router_kernel(
    const float* __restrict__ X, const float* __restrict__ Wr,
    const float* __restrict__ loop_table, const int* __restrict__ loop_idx)
{
    __shared__ float4 sW[NE][256];
    __shared__ float s_bias[NE];
    const int tid = threadIdx.x, warp = tid >> 5, lane = tid & 31;

    for (int i = tid; i < NE * 256; i += 256) {
        int e = i >> 8, k4 = i & 255;
        sW[e][k4] = make_float4(Wr[(size_t)(k4 * 4 + 0) * NE + e],
                                Wr[(size_t)(k4 * 4 + 1) * NE + e],
                                Wr[(size_t)(k4 * 4 + 2) * NE + e],
                                Wr[(size_t)(k4 * 4 + 3) * NE + e]);
    }
    const float* le = loop_table + (size_t)loop_idx[0] * DIM;
    float b = 0.f;
    for (int d = lane; d < DIM; d += 32)
        b += le[d] * Wr[(size_t)(DIM + d) * NE + warp];
    #pragma unroll
    for (int o = 16; o; o >>= 1) b += __shfl_xor_sync(~0u, b, o);
    if (lane == 0) s_bias[warp] = b;
    __syncthreads();

    const int t = blockIdx.x * 8 + warp;
    const float4* xr = (const float4*)(X + (size_t)t * DIM);
    float acc[NE];
    #pragma unroll
    for (int e = 0; e < NE; e++) acc[e] = 0.f;
    #pragma unroll 1
    for (int i = 0; i < 8; i++) {
        float4 xv = xr[lane + 32 * i];
        const float4* swp = &sW[0][lane + 32 * i];
        #pragma unroll
        for (int e = 0; e < NE; e++) {
            float4 w = swp[e * 256];
            acc[e] += xv.x * w.x + xv.y * w.y + xv.z * w.z + xv.w * w.w;
        }
    }
    #pragma unroll
    for (int e = 0; e < NE; e++)
        #pragma unroll
        for (int o = 16; o; o >>= 1) acc[e] += __shfl_xor_sync(~0u, acc[e], o);

    if (lane == 0) {
        float p[NE];
        #pragma unroll
        for (int e = 0; e < NE; e++)
            p[e] = 1.f / (1.f + expf(-(acc[e] + s_bias[e])));
        int i0 = 0; float v0 = p[0];
        #pragma unroll
        for (int e = 1; e < NE; e++) if (p[e] > v0) { v0 = p[e]; i0 = e; }
        int i1 = -1; float v1 = -1e30f;
        #pragma unroll
        for (int e = 0; e < NE; e++) {
            if (e == i0) continue;
            if (p[e] > v1) { v1 = p[e]; i1 = e; }
        }
        g_top_e[t * 2 + 0] = i0;  g_top_e[t * 2 + 1] = i1;
        g_top_w[t * 2 + 0] = v0;  g_top_w[t * 2 + 1] = v1;
    }
}

__global__ void dispatch_kernel() {
    int t = blockIdx.x * blockDim.x + threadIdx.x;
    if (t >= N_TOK) return;
    #pragma unroll
    for (int k = 0; k < 2; k++) {
        int e = g_top_e[t * 2 + k];
        int pos = atomicAdd(&g_cnt[e], 1);
        g_assign_token[e * N_TOK + pos] = t;
        g_assign_slot [e * N_TOK + pos] = k;
    }
}

// ---------------- GEMM1: X @ {Wg,Wu}[e] (fp32 B fused cvt), SiLU -> fp16 h --
// Block 128m x 64n, BK=32 per stage, 3-stage ring. A: cp.async fp16;
// B: LDG.128 fp32 -> cvt -> STS.128 fp16. A pitch 80B, B pitch 144B.
#define S1_A  0u
#define S1_G  10240u
#define S1_U  14848u
#define S1_STG 19456u

__global__ __launch_bounds__(256) void gemm1_kernel(
    const float* __restrict__ Wg, const float* __restrict__ Wu,
    const float* __restrict__ sgp, const float* __restrict__ sup)
{
    extern __shared__ char sm[];
    __shared__ int s_token[128];

    const int e   = blockIdx.z;
    const int cnt = g_cnt[e];
    const int m0  = blockIdx.y * 128;
    if (m0 >= cnt) return;
    const int n0  = blockIdx.x * 64;
    const int tid = threadIdx.x, wid = tid >> 5, lane = tid & 31;

    if (tid < 128) {
        int r = m0 + tid;
        s_token[tid] = (e < NE) ? ((r < cnt) ? g_assign_token[e * N_TOK + r] : 0) : r;
    }
    __syncthreads();
    const uint32_t sb = smem_u32(sm);

    // fp32 weight sources
    const float* wgF = (e < NE) ? Wg + (size_t)e * DIM * HID : sgp;
    const float* wuF = (e < NE) ? Wu + (size_t)e * DIM * HID : sup;

    // A loaders (cp.async fp16): 2 per thread per stage
    const int ar0 = tid >> 2, ac = (tid & 3) * 16;
    const char* aSrc0 = (const char*)(g_Xf + (size_t)s_token[ar0] * DIM) + ac;
    const char* aSrc1 = (const char*)(g_Xf + (size_t)s_token[64 + ar0] * DIM) + ac;
    const uint32_t aDst0 = sb + S1_A + ar0 * 80 + ac;
    const uint32_t aDst1 = sb + S1_A + (64 + ar0) * 80 + ac;

    // B loaders (fp32 LDG -> cvt -> STS): thread covers 16 k-values of one row
    const int bmat = tid >> 7;               // 0 = gate, 1 = up
    const int brw  = (tid & 127) >> 2;       // k-row within stage, 0..31
    const int bsub = tid & 3;                // 16-float chunk within row
    const float* bSrcF = (bmat ? wuF : wgF) + (size_t)brw * 1024 + n0 + bsub * 16;
    const uint32_t bOffBase = (bmat ? S1_U : S1_G) + brw * 144 + bsub * 32;

    float4 bv[4];
#define LDG_B(k0) do { \
        const float4* _p = (const float4*)(bSrcF + (size_t)(k0) * 1024); \
        bv[0] = _p[0]; bv[1] = _p[1]; bv[2] = _p[2]; bv[3] = _p[3]; } while (0)
#define STS_B(buf) do { \
        uint4* _d = (uint4*)(sm + bOffBase + (uint32_t)(buf) * S1_STG); \
        _d[0] = make_uint4(cvt2(bv[0].x, bv[0].y), cvt2(bv[0].z, bv[0].w), \
                           cvt2(bv[1].x, bv[1].y), cvt2(bv[1].z, bv[1].w)); \
        _d[1] = make_uint4(cvt2(bv[2].x, bv[2].y), cvt2(bv[2].z, bv[2].w), \
                           cvt2(bv[3].x, bv[3].y), cvt2(bv[3].z, bv[3].w)); } while (0)
#define LOAD_A(k0, buf) do { \
        uint32_t _o = (uint32_t)(buf) * S1_STG; \
        size_t _ab = (size_t)(k0) * 2; \
        CP_ASYNC16(aDst0 + _o, aSrc0 + _ab); \
        CP_ASYNC16(aDst1 + _o, aSrc1 + _ab); \
        CP_COMMIT(); } while (0)

    const int wm = (wid & 3) * 32, wn = (wid >> 2) * 32;
    const int am = (lane & 7) + ((lane >> 3) & 1) * 8;
    const uint32_t ako = (lane >> 4) * 16;
    const uint32_t aB = sb + S1_A + (wm + am) * 80 + ako;
    const int bk = lane & 15;
    const uint32_t bG = sb + S1_G + bk * 144 + wn * 2;
    const uint32_t bU = sb + S1_U + bk * 144 + wn * 2;

    float accG[2][4][4], accU[2][4][4];
    #pragma unroll
    for (int i = 0; i < 2; i++)
        #pragma unroll
        for (int j = 0; j < 4; j++)
            #pragma unroll
            for (int q = 0; q < 4; q++) { accG[i][j][q] = 0.f; accU[i][j][q] = 0.f; }

    // prologue: fill stages 0 and 1
    LDG_B(0);  STS_B(0);
    LDG_B(32); STS_B(1);
    LOAD_A(0, 0);
    LOAD_A(32, 1);
    CP_WAIT(1); __syncthreads();

    int cur = 0;
    for (int s = 0; s < 32; s++) {
        int ldb = cur + 2; if (ldb >= 3) ldb -= 3;
        if (s + 2 < 32) {
            LDG_B((s + 2) * 32);
            LOAD_A((s + 2) * 32, ldb);
        }

        const uint32_t off = (uint32_t)cur * S1_STG;
        #pragma unroll
        for (int ks = 0; ks < 2; ks++) {
            uint32_t a[2][4], bg[4][2], bu[4][2];
            #pragma unroll
            for (int i = 0; i < 2; i++)
                ldsm_x4(a[i], aB + off + ks * 32 + i * 1280);
            #pragma unroll
            for (int j = 0; j < 4; j++) {
                ldsm_x2_t(bg[j], bG + off + ks * 2304 + j * 16);
                ldsm_x2_t(bu[j], bU + off + ks * 2304 + j * 16);
            }
            #pragma unroll
            for (int i = 0; i < 2; i++)
                #pragma unroll
                for (int j = 0; j < 4; j++) {
                    mma_f16(accG[i][j], a[i], bg[j]);
                    mma_f16(accU[i][j], a[i], bu[j]);
                }
        }
        if (s + 2 < 32) { STS_B(ldb); CP_WAIT(1); }
        else            { CP_WAIT(0); }
        __syncthreads();
        cur++; if (cur == 3) cur = 0;
    }

    const int qr = lane >> 2, r4 = lane & 3;
    #pragma unroll
    for (int i = 0; i < 2; i++) {
        const int lr0 = wm + i * 16 + qr, lr1 = lr0 + 8;
        const bool ok0 = (m0 + lr0) < cnt, ok1 = (m0 + lr1) < cnt;
        __half* d0 = g_Hf + ((size_t)e * N_TOK + m0 + lr0) * HID + n0;
        __half* d1 = g_Hf + ((size_t)e * N_TOK + m0 + lr1) * HID + n0;
        #pragma unroll
        for (int j = 0; j < 4; j++) {
            const int col = wn + j * 8 + r4 * 2;
            float h00 = silu(accG[i][j][0]) * accU[i][j][0];
            float h01 = silu(accG[i][j][1]) * accU[i][j][1];
            float h10 = silu(accG[i][j][2]) * accU[i][j][2];
            float h11 = silu(accG[i][j][3]) * accU[i][j][3];
            if (ok0) *(uint32_t*)(d0 + col) = cvt2(h00, h01);
            if (ok1) *(uint32_t*)(d1 + col) = cvt2(h10, h11);
        }
    }
#undef LDG_B
#undef STS_B
#undef LOAD_A
}

// ---------------- GEMM2: h @ Wd[e] -> scattered fp32 rbuf -------------------
// Block 128m x 64n, BK=32 per stage, 3-stage (as R12).
#define S2_A  0u
#define S2_B  10240u
#define S2_STG 14848u

__global__ __launch_bounds__(256) void gemm2_kernel() {
    extern __shared__ char sm[];
    __shared__ int s_dst[128];

    const int e   = blockIdx.z;
    const int cnt = g_cnt[e];
    const int m0  = blockIdx.y * 128;
    if (m0 >= cnt) return;
    const int n0  = blockIdx.x * 64;
    const int tid = threadIdx.x, wid = tid >> 5, lane = tid & 31;

    const int id = (e < NE) ? e : 8;

    if (tid < 128) {
        int r = m0 + tid, dst = 0;
        if (r < cnt) {
            if (e < NE)
                dst = g_assign_slot[e * N_TOK + r] * N_TOK + g_assign_token[e * N_TOK + r];
            else
                dst = 2 * N_TOK + r;
        }
        s_dst[tid] = dst;
    }
    __syncthreads();
    const uint32_t sb = smem_u32(sm);

    const char* wd = (const char*)(g_Wdf + (size_t)id * DIM * HID);

    const int ar0 = tid >> 2, ac = (tid & 3) * 16;
    const char* aSrc0 = (const char*)(g_Hf + ((size_t)e * N_TOK + m0 + ar0) * HID) + ac;
    const char* aSrc1 = (const char*)(g_Hf + ((size_t)e * N_TOK + m0 + 64 + ar0) * HID) + ac;
    const uint32_t aDst0 = sb + S2_A + ar0 * 80 + ac;
    const uint32_t aDst1 = sb + S2_A + (64 + ar0) * 80 + ac;
    const int brw = tid >> 3, bcc = (tid & 7) * 16;
    const char* bSrc = wd + (size_t)brw * DIM * 2 + n0 * 2 + bcc;
    const uint32_t bDst = sb + S2_B + brw * 144 + bcc;

#define G_LOAD(k0, buf) do { \
        uint32_t _o = (uint32_t)(buf) * S2_STG; \
        size_t _ab = (size_t)(k0) * 2; \
        size_t _bb = (size_t)(k0) * DIM * 2; \
        CP_ASYNC16(aDst0 + _o, aSrc0 + _ab); \
        CP_ASYNC16(aDst1 + _o, aSrc1 + _ab); \
        CP_ASYNC16(bDst + _o, bSrc + _bb); \
        CP_COMMIT(); } while (0)

    const int wm = (wid & 3) * 32, wn = (wid >> 2) * 32;
    const int am = (lane & 7) + ((lane >> 3) & 1) * 8;
    const uint32_t ako = (lane >> 4) * 16;
    const uint32_t aB = sb + S2_A + (wm + am) * 80 + ako;
    const int bk = lane & 15;
    const uint32_t bB = sb + S2_B + bk * 144 + wn * 2;

    float acc[2][4][4];
    #pragma unroll
    for (int i = 0; i < 2; i++)
        #pragma unroll
        for (int j = 0; j < 4; j++)
            #pragma unroll
            for (int q = 0; q < 4; q++) acc[i][j][q] = 0.f;

    G_LOAD(0, 0);
    G_LOAD(32, 1);
    CP_WAIT(1); __syncthreads();

    int cur = 0;
    for (int s = 0; s < 32; s++) {
        int ldb = cur + 2; if (ldb >= 3) ldb -= 3;
        if (s + 2 < 32) G_LOAD((s + 2) * 32, ldb);

        const uint32_t off = (uint32_t)cur * S2_STG;
        #pragma unroll
        for (int ks = 0; ks < 2; ks++) {
            uint32_t a[2][4], b[4][2];
            #pragma unroll
            for (int i = 0; i < 2; i++)
                ldsm_x4(a[i], aB + off + ks * 32 + i * 1280);
            #pragma unroll
            for (int j = 0; j < 4; j++)
                ldsm_x2_t(b[j], bB + off + ks * 2304 + j * 16);
            #pragma unroll
            for (int i = 0; i < 2; i++)
                #pragma unroll
                for (int j = 0; j < 4; j++)
                    mma_f16(acc[i][j], a[i], b[j]);
        }
        if (s + 2 < 32) CP_WAIT(1); else CP_WAIT(0);
        __syncthreads();
        cur++; if (cur == 3) cur = 0;
    }

    const int qr = lane >> 2, r4 = lane & 3;
    #pragma unroll
    for (int i = 0; i < 2; i++) {
        const int lr0 = wm + i * 16 + qr, lr1 = lr0 + 8;
        const bool ok0 = (m0 + lr0) < cnt, ok1 = (m0 + lr1) < cnt;
        float* d0 = g_rbuf + (size_t)s_dst[lr0] * DIM + n0;
        float* d1 = g_rbuf + (size_t)s_dst[lr1] * DIM + n0;
        #pragma unroll
        for (int j = 0; j < 4; j++) {
            const int col = wn + j * 8 + r4 * 2;
            if (ok0) *(float2*)(d0 + col) = make_float2(acc[i][j][0], acc[i][j][1]);
            if (ok1) *(float2*)(d1 + col) = make_float2(acc[i][j][2], acc[i][j][3]);
        }
    }
#undef G_LOAD
}

// ---------------- combine ---------------------------------------------------
__global__ void combine_kernel(float* __restrict__ out) {
    int i4 = blockIdx.x * 256 + threadIdx.x;
    int t  = i4 >> 8;
    float w0 = g_top_w[2 * t], w1 = g_top_w[2 * t + 1];
    float4 a = ((const float4*)g_rbuf)[i4];
    float4 b = ((const float4*)g_rbuf)[(size_t)(N_TOK * DIM / 4) + i4];
    float4 c = ((const float4*)g_rbuf)[(size_t)(2 * N_TOK * DIM / 4) + i4];
    float4 o;
    o.x = c.x + w0 * a.x + w1 * b.x;
    o.y = c.y + w0 * a.y + w1 * b.y;
    o.z = c.z + w0 * a.z + w1 * b.z;
    o.w = c.w + w0 * a.w + w1 * b.w;
    ((float4*)out)[i4] = o;
}

// ---------------- launch ----------------------------------------------------
extern "C" void kernel_launch(void* const* d_in, const int* in_sizes, int n_in,
                              void* d_out, int out_size)
{
    const float* x  = (const float*)d_in[0];
    const float* sg = (const float*)d_in[1];
    const float* su = (const float*)d_in[2];
    const float* sd = (const float*)d_in[3];
    const float* Wg = (const float*)d_in[4];
    const float* Wu = (const float*)d_in[5];
    const float* Wd = (const float*)d_in[6];
    const float* Wr = (const float*)d_in[7];
    const float* lt = (const float*)d_in[8];
    const int*   li = (const int*)d_in[9];
    float* out = (float*)d_out;
    (void)in_sizes; (void)n_in; (void)out_size;

    static cudaStream_t s2 = nullptr;
    static cudaEvent_t evFork = nullptr, evX = nullptr, evD = nullptr;
    static int init_done = 0;
    if (!init_done) {
        cudaFuncSetAttribute(gemm1_kernel, cudaFuncAttributeMaxDynamicSharedMemorySize, 3 * S1_STG);
        cudaFuncSetAttribute(gemm2_kernel, cudaFuncAttributeMaxDynamicSharedMemorySize, 3 * S2_STG);
        cudaStreamCreateWithFlags(&s2, cudaStreamNonBlocking);
        cudaEventCreateWithFlags(&evFork, cudaEventDisableTiming);
        cudaEventCreateWithFlags(&evX, cudaEventDisableTiming);
        cudaEventCreateWithFlags(&evD, cudaEventDisableTiming);
        init_done = 1;
    }

    cudaEventRecord(evFork, 0);
    cudaStreamWaitEvent(s2, evFork, 0);

    zero_kernel<<<1, 32>>>();
    router_kernel<<<N_TOK / 8, 256>>>(x, Wr, lt, li);
    dispatch_kernel<<<N_TOK / 256, 256>>>();

    convert_x_kernel<<<(N_TOK * DIM / 4) / 1024, 256, 0, s2>>>(x);
    cudaEventRecord(evX, s2);
    convert_w_d_kernel<<<dim3((DIM * HID / 4) / 1024, 9), 256, 0, s2>>>(Wd, sd);
    cudaEventRecord(evD, s2);

    cudaStreamWaitEvent(0, evX, 0);
    gemm1_kernel<<<dim3(16, 32, NSEG), 256, 3 * S1_STG>>>(Wg, Wu, sg, su);
    cudaStreamWaitEvent(0, evD, 0);
    gemm2_kernel<<<dim3(16, 32, NSEG), 256, 3 * S2_STG>>>();
    combine_kernel<<<(N_TOK * (DIM / 4)) / 256, 256>>>(out);
}

// round 15
// speedup vs baseline: 1.2940x; 1.2940x over previous
#include <cuda_runtime.h>
#include <cuda_fp16.h>
#include <cstdint>

#define N_TOK 4096
#define DIM   1024
#define HID   1024
#define NE    8
#define NSEG  9

// ---------------- scratch ---------------------------------------------------
__device__ int   g_cnt[NSEG];
__device__ int   g_assign_token[NE * N_TOK];
__device__ int   g_assign_slot [NE * N_TOK];
__device__ int   g_top_e[N_TOK * 2];
__device__ float g_top_w[N_TOK * 2];
__device__ __half g_Xf[(size_t)N_TOK * DIM];
// 27 matrices [k][n]: Wg[0..7], Wu[8..15], Wd[16..23], sg=24, su=25, sd=26
__device__ __half g_Wf[(size_t)27 * DIM * HID];
__device__ __half g_Hf[(size_t)NSEG * N_TOK * HID];
__device__ float g_rbuf[(size_t)3 * N_TOK * DIM];

// ---------------- helpers ---------------------------------------------------
__device__ __forceinline__ uint32_t smem_u32(const void* p) {
    uint32_t a;
    asm("{ .reg .u64 t; cvta.to.shared.u64 t, %1; cvt.u32.u64 %0, t; }"
        : "=r"(a) : "l"(p));
    return a;
}
#define CP_ASYNC16(dst, src) \
    asm volatile("cp.async.cg.shared.global [%0], [%1], 16;" :: "r"(dst), "l"(src))
#define CP_COMMIT() asm volatile("cp.async.commit_group;" ::: "memory")
#define CP_WAIT(n)  asm volatile("cp.async.wait_group %0;" :: "n"(n) : "memory")

__device__ __forceinline__ void ldsm_x4(uint32_t* r, uint32_t addr) {
    asm volatile("ldmatrix.sync.aligned.m8n8.x4.shared.b16 {%0,%1,%2,%3}, [%4];"
        : "=r"(r[0]), "=r"(r[1]), "=r"(r[2]), "=r"(r[3]) : "r"(addr));
}
__device__ __forceinline__ void ldsm_x2_t(uint32_t* r, uint32_t addr) {
    asm volatile("ldmatrix.sync.aligned.m8n8.x2.trans.shared.b16 {%0,%1}, [%2];"
        : "=r"(r[0]), "=r"(r[1]) : "r"(addr));
}
__device__ __forceinline__ void mma_f16(float* d, const uint32_t* a, const uint32_t* b) {
    asm volatile(
        "mma.sync.aligned.m16n8k16.row.col.f32.f16.f16.f32 "
        "{%0,%1,%2,%3}, {%4,%5,%6,%7}, {%8,%9}, {%0,%1,%2,%3};"
        : "+f"(d[0]), "+f"(d[1]), "+f"(d[2]), "+f"(d[3])
        : "r"(a[0]), "r"(a[1]), "r"(a[2]), "r"(a[3]), "r"(b[0]), "r"(b[1]));
}
__device__ __forceinline__ float silu(float g) { return g / (1.f + __expf(-g)); }

__device__ __forceinline__ void convert_one(const float* __restrict__ src,
                                            int m, size_t i4)
{
    float4 v = ((const float4*)src)[i4];
    __half2 a = __floats2half2_rn(v.x, v.y);
    __half2 b = __floats2half2_rn(v.z, v.w);
    size_t o = (size_t)m * (DIM * HID / 4) + i4;
    ((uint2*)g_Wf)[o] = make_uint2(*(uint32_t*)&a, *(uint32_t*)&b);
}

// ---------------- small kernels ---------------------------------------------
__global__ void zero_kernel() {
    int t = threadIdx.x;
    if (t < NE) g_cnt[t] = 0;
    if (t == NE) g_cnt[NE] = N_TOK;
}

__global__ void convert_x_kernel(const float* __restrict__ x) {
    size_t base = (size_t)blockIdx.x * 1024 + threadIdx.x;
    float4 v[4];
    #pragma unroll
    for (int j = 0; j < 4; j++) v[j] = ((const float4*)x)[base + j * 256];
    #pragma unroll
    for (int j = 0; j < 4; j++) {
        __half2 a = __floats2half2_rn(v[j].x, v[j].y);
        __half2 b = __floats2half2_rn(v[j].z, v[j].w);
        ((uint2*)g_Xf)[base + j * 256] = make_uint2(*(uint32_t*)&a, *(uint32_t*)&b);
    }
}

// gate/up matrices (18): indices 0..15, 24, 25
__global__ void convert_w_gu_kernel(
    const float* __restrict__ Wg, const float* __restrict__ Wu,
    const float* __restrict__ sg, const float* __restrict__ su)
{
    int by = blockIdx.y;
    int m = (by < 16) ? by : 24 + (by - 16);
    const float* src;
    if      (by < 8)  src = Wg + (size_t)by * DIM * HID;
    else if (by < 16) src = Wu + (size_t)(by - 8) * DIM * HID;
    else if (by == 16) src = sg;
    else               src = su;
    size_t base = (size_t)blockIdx.x * 1024 + threadIdx.x;
    #pragma unroll
    for (int j = 0; j < 4; j++) convert_one(src, m, base + j * 256);
}

// down matrices (9): indices 16..23, 26
__global__ void convert_w_d_kernel(
    const float* __restrict__ Wd, const float* __restrict__ sd)
{
    int by = blockIdx.y;
    int m = (by < 8) ? 16 + by : 26;
    const float* src = (by < 8) ? Wd + (size_t)by * DIM * HID : sd;
    size_t base = (size_t)blockIdx.x * 1024 + threadIdx.x;
    #pragma unroll
    for (int j = 0; j < 4; j++) convert_one(src, m, base + j * 256);
}

// router: 1 token per warp, 512 blocks
__global__ __launch_bounds__(256, 4) void router_kernel(
    const float* __restrict__ X, const float* __restrict__ Wr,
    const float* __restrict__ loop_table, const int* __restrict__ loop_idx)
{
    __shared__ float4 sW[NE][256];
    __shared__ float s_bias[NE];
    const int tid = threadIdx.x, warp = tid >> 5, lane = tid & 31;

    for (int i = tid; i < NE * 256; i += 256) {
        int e = i >> 8, k4 = i & 255;
        sW[e][k4] = make_float4(Wr[(size_t)(k4 * 4 + 0) * NE + e],
                                Wr[(size_t)(k4 * 4 + 1) * NE + e],
                                Wr[(size_t)(k4 * 4 + 2) * NE + e],
                                Wr[(size_t)(k4 * 4 + 3) * NE + e]);
    }
    const float* le = loop_table + (size_t)loop_idx[0] * DIM;
    float b = 0.f;
    for (int d = lane; d < DIM; d += 32)
        b += le[d] * Wr[(size_t)(DIM + d) * NE + warp];
    #pragma unroll
    for (int o = 16; o; o >>= 1) b += __shfl_xor_sync(~0u, b, o);
    if (lane == 0) s_bias[warp] = b;
    __syncthreads();

    const int t = blockIdx.x * 8 + warp;
    const float4* xr = (const float4*)(X + (size_t)t * DIM);
    float acc[NE];
    #pragma unroll
    for (int e = 0; e < NE; e++) acc[e] = 0.f;
    #pragma unroll 1
    for (int i = 0; i < 8; i++) {
        float4 xv = xr[lane + 32 * i];
        const float4* swp = &sW[0][lane + 32 * i];
        #pragma unroll
        for (int e = 0; e < NE; e++) {
            float4 w = swp[e * 256];
            acc[e] += xv.x * w.x + xv.y * w.y + xv.z * w.z + xv.w * w.w;
        }
    }
    #pragma unroll
    for (int e = 0; e < NE; e++)
        #pragma unroll
        for (int o = 16; o; o >>= 1) acc[e] += __shfl_xor_sync(~0u, acc[e], o);

    if (lane == 0) {
        float p[NE];
        #pragma unroll
        for (int e = 0; e < NE; e++)
            p[e] = 1.f / (1.f + expf(-(acc[e] + s_bias[e])));
        int i0 = 0; float v0 = p[0];
        #pragma unroll
        for (int e = 1; e < NE; e++) if (p[e] > v0) { v0 = p[e]; i0 = e; }
        int i1 = -1; float v1 = -1e30f;
        #pragma unroll
        for (int e = 0; e < NE; e++) {
            if (e == i0) continue;
            if (p[e] > v1) { v1 = p[e]; i1 = e; }
        }
        g_top_e[t * 2 + 0] = i0;  g_top_e[t * 2 + 1] = i1;
        g_top_w[t * 2 + 0] = v0;  g_top_w[t * 2 + 1] = v1;
    }
}

__global__ void dispatch_kernel() {
    int t = blockIdx.x * blockDim.x + threadIdx.x;
    if (t >= N_TOK) return;
    #pragma unroll
    for (int k = 0; k < 2; k++) {
        int e = g_top_e[t * 2 + k];
        int pos = atomicAdd(&g_cnt[e], 1);
        g_assign_token[e * N_TOK + pos] = t;
        g_assign_slot [e * N_TOK + pos] = k;
    }
}

// ---------------- GEMM1: X @ {Wg,Wu}[e], fused SiLU -> fp16 h ---------------
// Block 128m x 64n, BK=32 per stage, 3-stage. A pitch 80B, B pitch 144B.
#define S1_A  0u
#define S1_G  10240u
#define S1_U  14848u
#define S1_STG 19456u

__global__ __launch_bounds__(256) void gemm1_kernel() {
    extern __shared__ char sm[];
    __shared__ int s_token[128];

    const int e   = blockIdx.z;
    const int cnt = g_cnt[e];
    const int m0  = blockIdx.y * 128;
    if (m0 >= cnt) return;
    const int n0  = blockIdx.x * 64;
    const int tid = threadIdx.x, wid = tid >> 5, lane = tid & 31;

    const int ig = (e < NE) ? e : 24;
    const int iu = (e < NE) ? 8 + e : 25;

    if (tid < 128) {
        int r = m0 + tid;
        s_token[tid] = (e < NE) ? ((r < cnt) ? g_assign_token[e * N_TOK + r] : 0) : r;
    }
    __syncthreads();
    const uint32_t sb = smem_u32(sm);

    const char* wg = (const char*)(g_Wf + (size_t)ig * DIM * HID);
    const char* wu = (const char*)(g_Wf + (size_t)iu * DIM * HID);

    const int ar0 = tid >> 2, ac = (tid & 3) * 16;
    const char* aSrc0 = (const char*)(g_Xf + (size_t)s_token[ar0] * DIM) + ac;
    const char* aSrc1 = (const char*)(g_Xf + (size_t)s_token[64 + ar0] * DIM) + ac;
    const uint32_t aDst0 = sb + S1_A + ar0 * 80 + ac;
    const uint32_t aDst1 = sb + S1_A + (64 + ar0) * 80 + ac;
    const int brw = tid >> 3, bcc = (tid & 7) * 16;
    const char* gSrc = wg + (size_t)brw * HID * 2 + n0 * 2 + bcc;
    const char* uSrc = wu + (size_t)brw * HID * 2 + n0 * 2 + bcc;
    const uint32_t gDst = sb + S1_G + brw * 144 + bcc;
    const uint32_t uDst = sb + S1_U + brw * 144 + bcc;

#define G_LOAD(k0, buf) do { \
        uint32_t _o = (uint32_t)(buf) * S1_STG; \
        size_t _ab = (size_t)(k0) * 2; \
        size_t _bb = (size_t)(k0) * HID * 2; \
        CP_ASYNC16(aDst0 + _o, aSrc0 + _ab); \
        CP_ASYNC16(aDst1 + _o, aSrc1 + _ab); \
        CP_ASYNC16(gDst + _o, gSrc + _bb); \
        CP_ASYNC16(uDst + _o, uSrc + _bb); \
        CP_COMMIT(); } while (0)

    const int wm = (wid & 3) * 32, wn = (wid >> 2) * 32;
    const int am = (lane & 7) + ((lane >> 3) & 1) * 8;
    const uint32_t ako = (lane >> 4) * 16;
    const uint32_t aB = sb + S1_A + (wm + am) * 80 + ako;
    const int bk = lane & 15;
    const uint32_t bG = sb + S1_G + bk * 144 + wn * 2;
    const uint32_t bU = sb + S1_U + bk * 144 + wn * 2;

    float accG[2][4][4], accU[2][4][4];
    #pragma unroll
    for (int i = 0; i < 2; i++)
        #pragma unroll
        for (int j = 0; j < 4; j++)
            #pragma unroll
            for (int q = 0; q < 4; q++) { accG[i][j][q] = 0.f; accU[i][j][q] = 0.f; }

    G_LOAD(0, 0);
    G_LOAD(32, 1);
    CP_WAIT(1); __syncthreads();

    int cur = 0;
    for (int s = 0; s < 32; s++) {
        int ldb = cur + 2; if (ldb >= 3) ldb -= 3;
        if (s + 2 < 32) G_LOAD((s + 2) * 32, ldb);

        const uint32_t off = (uint32_t)cur * S1_STG;
        #pragma unroll
        for (int ks = 0; ks < 2; ks++) {
            uint32_t a[2][4], bg[4][2], bu[4][2];
            #pragma unroll
            for (int i = 0; i < 2; i++)
                ldsm_x4(a[i], aB + off + ks * 32 + i * 1280);
            #pragma unroll
            for (int j = 0; j < 4; j++) {
                ldsm_x2_t(bg[j], bG + off + ks * 2304 + j * 16);
                ldsm_x2_t(bu[j], bU + off + ks * 2304 + j * 16);
            }
            #pragma unroll
            for (int i = 0; i < 2; i++)
                #pragma unroll
                for (int j = 0; j < 4; j++) {
                    mma_f16(accG[i][j], a[i], bg[j]);
                    mma_f16(accU[i][j], a[i], bu[j]);
                }
        }
        if (s + 2 < 32) CP_WAIT(1); else CP_WAIT(0);
        __syncthreads();
        cur++; if (cur == 3) cur = 0;
    }

    const int qr = lane >> 2, r4 = lane & 3;
    #pragma unroll
    for (int i = 0; i < 2; i++) {
        const int lr0 = wm + i * 16 + qr, lr1 = lr0 + 8;
        const bool ok0 = (m0 + lr0) < cnt, ok1 = (m0 + lr1) < cnt;
        __half* d0 = g_Hf + ((size_t)e * N_TOK + m0 + lr0) * HID + n0;
        __half* d1 = g_Hf + ((size_t)e * N_TOK + m0 + lr1) * HID + n0;
        #pragma unroll
        for (int j = 0; j < 4; j++) {
            const int col = wn + j * 8 + r4 * 2;
            float h00 = silu(accG[i][j][0]) * accU[i][j][0];
            float h01 = silu(accG[i][j][1]) * accU[i][j][1];
            float h10 = silu(accG[i][j][2]) * accU[i][j][2];
            float h11 = silu(accG[i][j][3]) * accU[i][j][3];
            if (ok0) *(__half2*)(d0 + col) = __floats2half2_rn(h00, h01);
            if (ok1) *(__half2*)(d1 + col) = __floats2half2_rn(h10, h11);
        }
    }
#undef G_LOAD
}

// ---------------- GEMM2: h @ Wd[e] -> scattered fp32 rbuf -------------------
// Block 128m x 64n, BK=32 per stage, 3-stage.
#define S2_A  0u
#define S2_B  10240u
#define S2_STG 14848u

__global__ __launch_bounds__(256) void gemm2_kernel() {
    extern __shared__ char sm[];
    __shared__ int s_dst[128];

    const int e   = blockIdx.z;
    const int cnt = g_cnt[e];
    const int m0  = blockIdx.y * 128;
    if (m0 >= cnt) return;
    const int n0  = blockIdx.x * 64;
    const int tid = threadIdx.x, wid = tid >> 5, lane = tid & 31;

    const int id = (e < NE) ? 16 + e : 26;

    if (tid < 128) {
        int r = m0 + tid, dst = 0;
        if (r < cnt) {
            if (e < NE)
                dst = g_assign_slot[e * N_TOK + r] * N_TOK + g_assign_token[e * N_TOK + r];
            else
                dst = 2 * N_TOK + r;
        }
        s_dst[tid] = dst;
    }
    __syncthreads();
    const uint32_t sb = smem_u32(sm);

    const char* wd = (const char*)(g_Wf + (size_t)id * DIM * HID);

    const int ar0 = tid >> 2, ac = (tid & 3) * 16;
    const char* aSrc0 = (const char*)(g_Hf + ((size_t)e * N_TOK + m0 + ar0) * HID) + ac;
    const char* aSrc1 = (const char*)(g_Hf + ((size_t)e * N_TOK + m0 + 64 + ar0) * HID) + ac;
    const uint32_t aDst0 = sb + S2_A + ar0 * 80 + ac;
    const uint32_t aDst1 = sb + S2_A + (64 + ar0) * 80 + ac;
    const int brw = tid >> 3, bcc = (tid & 7) * 16;
    const char* bSrc = wd + (size_t)brw * DIM * 2 + n0 * 2 + bcc;
    const uint32_t bDst = sb + S2_B + brw * 144 + bcc;

#define G_LOAD(k0, buf) do { \
        uint32_t _o = (uint32_t)(buf) * S2_STG; \
        size_t _ab = (size_t)(k0) * 2; \
        size_t _bb = (size_t)(k0) * DIM * 2; \
        CP_ASYNC16(aDst0 + _o, aSrc0 + _ab); \
        CP_ASYNC16(aDst1 + _o, aSrc1 + _ab); \
        CP_ASYNC16(bDst + _o, bSrc + _bb); \
        CP_COMMIT(); } while (0)

    const int wm = (wid & 3) * 32, wn = (wid >> 2) * 32;
    const int am = (lane & 7) + ((lane >> 3) & 1) * 8;
    const uint32_t ako = (lane >> 4) * 16;
    const uint32_t aB = sb + S2_A + (wm + am) * 80 + ako;
    const int bk = lane & 15;
    const uint32_t bB = sb + S2_B + bk * 144 + wn * 2;

    float acc[2][4][4];
    #pragma unroll
    for (int i = 0; i < 2; i++)
        #pragma unroll
        for (int j = 0; j < 4; j++)
            #pragma unroll
            for (int q = 0; q < 4; q++) acc[i][j][q] = 0.f;

    G_LOAD(0, 0);
    G_LOAD(32, 1);
    CP_WAIT(1); __syncthreads();

    int cur = 0;
    for (int s = 0; s < 32; s++) {
        int ldb = cur + 2; if (ldb >= 3) ldb -= 3;
        if (s + 2 < 32) G_LOAD((s + 2) * 32, ldb);

        const uint32_t off = (uint32_t)cur * S2_STG;
        #pragma unroll
        for (int ks = 0; ks < 2; ks++) {
            uint32_t a[2][4], b[4][2];
            #pragma unroll
            for (int i = 0; i < 2; i++)
                ldsm_x4(a[i], aB + off + ks * 32 + i * 1280);
            #pragma unroll
            for (int j = 0; j < 4; j++)
                ldsm_x2_t(b[j], bB + off + ks * 2304 + j * 16);
            #pragma unroll
            for (int i = 0; i < 2; i++)
                #pragma unroll
                for (int j = 0; j < 4; j++)
                    mma_f16(acc[i][j], a[i], b[j]);
        }
        if (s + 2 < 32) CP_WAIT(1); else CP_WAIT(0);
        __syncthreads();
        cur++; if (cur == 3) cur = 0;
    }

    const int qr = lane >> 2, r4 = lane & 3;
    #pragma unroll
    for (int i = 0; i < 2; i++) {
        const int lr0 = wm + i * 16 + qr, lr1 = lr0 + 8;
        const bool ok0 = (m0 + lr0) < cnt, ok1 = (m0 + lr1) < cnt;
        float* d0 = g_rbuf + (size_t)s_dst[lr0] * DIM + n0;
        float* d1 = g_rbuf + (size_t)s_dst[lr1] * DIM + n0;
        #pragma unroll
        for (int j = 0; j < 4; j++) {
            const int col = wn + j * 8 + r4 * 2;
            if (ok0) *(float2*)(d0 + col) = make_float2(acc[i][j][0], acc[i][j][1]);
            if (ok1) *(float2*)(d1 + col) = make_float2(acc[i][j][2], acc[i][j][3]);
        }
    }
#undef G_LOAD
}

// ---------------- combine ---------------------------------------------------
__global__ void combine_kernel(float* __restrict__ out) {
    int i4 = blockIdx.x * 256 + threadIdx.x;
    int t  = i4 >> 8;
    float w0 = g_top_w[2 * t], w1 = g_top_w[2 * t + 1];
    float4 a = ((const float4*)g_rbuf)[i4];
    float4 b = ((const float4*)g_rbuf)[(size_t)(N_TOK * DIM / 4) + i4];
    float4 c = ((const float4*)g_rbuf)[(size_t)(2 * N_TOK * DIM / 4) + i4];
    float4 o;
    o.x = c.x + w0 * a.x + w1 * b.x;
    o.y = c.y + w0 * a.y + w1 * b.y;
    o.z = c.z + w0 * a.z + w1 * b.z;
    o.w = c.w + w0 * a.w + w1 * b.w;
    ((float4*)out)[i4] = o;
}

// ---------------- launch ----------------------------------------------------
extern "C" void kernel_launch(void* const* d_in, const int* in_sizes, int n_in,
                              void* d_out, int out_size)
{
    const float* x  = (const float*)d_in[0];
    const float* sg = (const float*)d_in[1];
    const float* su = (const float*)d_in[2];
    const float* sd = (const float*)d_in[3];
    const float* Wg = (const float*)d_in[4];
    const float* Wu = (const float*)d_in[5];
    const float* Wd = (const float*)d_in[6];
    const float* Wr = (const float*)d_in[7];
    const float* lt = (const float*)d_in[8];
    const int*   li = (const int*)d_in[9];
    float* out = (float*)d_out;
    (void)in_sizes; (void)n_in; (void)out_size;

    static cudaStream_t s2 = nullptr;
    static cudaEvent_t evFork = nullptr, evGU = nullptr, evD = nullptr;
    static int init_done = 0;
    if (!init_done) {
        cudaFuncSetAttribute(gemm1_kernel, cudaFuncAttributeMaxDynamicSharedMemorySize, 3 * S1_STG);
        cudaFuncSetAttribute(gemm2_kernel, cudaFuncAttributeMaxDynamicSharedMemorySize, 3 * S2_STG);
        cudaStreamCreateWithFlags(&s2, cudaStreamNonBlocking);
        cudaEventCreateWithFlags(&evFork, cudaEventDisableTiming);
        cudaEventCreateWithFlags(&evGU, cudaEventDisableTiming);
        cudaEventCreateWithFlags(&evD, cudaEventDisableTiming);
        init_done = 1;
    }

    // fork: s2 converts weights only; main does convert_x + routing chain.
    cudaEventRecord(evFork, 0);
    cudaStreamWaitEvent(s2, evFork, 0);

    convert_w_gu_kernel<<<dim3((DIM * HID / 4) / 1024, 18), 256, 0, s2>>>(Wg, Wu, sg, su);
    cudaEventRecord(evGU, s2);
    convert_w_d_kernel<<<dim3((DIM * HID / 4) / 1024, 9), 256, 0, s2>>>(Wd, sd);
    cudaEventRecord(evD, s2);

    zero_kernel<<<1, 32>>>();
    convert_x_kernel<<<(N_TOK * DIM / 4) / 1024, 256>>>(x);
    router_kernel<<<N_TOK / 8, 256>>>(x, Wr, lt, li);
    dispatch_kernel<<<N_TOK / 256, 256>>>();

    cudaStreamWaitEvent(0, evGU, 0);
    gemm1_kernel<<<dim3(16, 32, NSEG), 256, 3 * S1_STG>>>();
    cudaStreamWaitEvent(0, evD, 0);
    gemm2_kernel<<<dim3(16, 32, NSEG), 256, 3 * S2_STG>>>();
    combine_kernel<<<(N_TOK * (DIM / 4)) / 256, 256>>>(out);
}

// round 16
// speedup vs baseline: 1.3572x; 1.0488x over previous
#include <cuda_runtime.h>
#include <cuda_fp16.h>
#include <cstdint>

#define N_TOK 4096
#define DIM   1024
#define HID   1024
#define NE    8
#define NSEG  9

// ---------------- scratch ---------------------------------------------------
__device__ int   g_cnt[NSEG];
__device__ int   g_assign_token[NE * N_TOK];
__device__ int   g_assign_slot [NE * N_TOK];
__device__ int   g_top_e[N_TOK * 2];
__device__ float g_top_w[N_TOK * 2];
__device__ __half g_Xf[(size_t)N_TOK * DIM];
// 27 matrices [k][n]: Wg[0..7], Wu[8..15], Wd[16..23], sg=24, su=25, sd=26
__device__ __half g_Wf[(size_t)27 * DIM * HID];
__device__ __half g_Hf[(size_t)NSEG * N_TOK * HID];
__device__ float g_rbuf[(size_t)3 * N_TOK * DIM];

// ---------------- helpers ---------------------------------------------------
__device__ __forceinline__ uint32_t smem_u32(const void* p) {
    uint32_t a;
    asm("{ .reg .u64 t; cvta.to.shared.u64 t, %1; cvt.u32.u64 %0, t; }"
        : "=r"(a) : "l"(p));
    return a;
}
#define CP_ASYNC16(dst, src) \
    asm volatile("cp.async.cg.shared.global [%0], [%1], 16;" :: "r"(dst), "l"(src))
#define CP_COMMIT() asm volatile("cp.async.commit_group;" ::: "memory")
#define CP_WAIT(n)  asm volatile("cp.async.wait_group %0;" :: "n"(n) : "memory")

__device__ __forceinline__ void ldsm_x4(uint32_t* r, uint32_t addr) {
    asm volatile("ldmatrix.sync.aligned.m8n8.x4.shared.b16 {%0,%1,%2,%3}, [%4];"
        : "=r"(r[0]), "=r"(r[1]), "=r"(r[2]), "=r"(r[3]) : "r"(addr));
}
__device__ __forceinline__ void ldsm_x2_t(uint32_t* r, uint32_t addr) {
    asm volatile("ldmatrix.sync.aligned.m8n8.x2.trans.shared.b16 {%0,%1}, [%2];"
        : "=r"(r[0]), "=r"(r[1]) : "r"(addr));
}
__device__ __forceinline__ void mma_f16(float* d, const uint32_t* a, const uint32_t* b) {
    asm volatile(
        "mma.sync.aligned.m16n8k16.row.col.f32.f16.f16.f32 "
        "{%0,%1,%2,%3}, {%4,%5,%6,%7}, {%8,%9}, {%0,%1,%2,%3};"
        : "+f"(d[0]), "+f"(d[1]), "+f"(d[2]), "+f"(d[3])
        : "r"(a[0]), "r"(a[1]), "r"(a[2]), "r"(a[3]), "r"(b[0]), "r"(b[1]));
}
__device__ __forceinline__ float silu(float g) { return g / (1.f + __expf(-g)); }

__device__ __forceinline__ void convert_one(const float* __restrict__ src,
                                            int m, size_t i4)
{
    float4 v = ((const float4*)src)[i4];
    __half2 a = __floats2half2_rn(v.x, v.y);
    __half2 b = __floats2half2_rn(v.z, v.w);
    size_t o = (size_t)m * (DIM * HID / 4) + i4;
    ((uint2*)g_Wf)[o] = make_uint2(*(uint32_t*)&a, *(uint32_t*)&b);
}

// ---------------- small kernels ---------------------------------------------
__global__ void zero_kernel() {
    int t = threadIdx.x;
    if (t < NE) g_cnt[t] = 0;
    if (t == NE) g_cnt[NE] = N_TOK;
}

// gate/up matrices (18): indices 0..15, 24, 25
__global__ void convert_w_gu_kernel(
    const float* __restrict__ Wg, const float* __restrict__ Wu,
    const float* __restrict__ sg, const float* __restrict__ su)
{
    int by = blockIdx.y;
    int m = (by < 16) ? by : 24 + (by - 16);
    const float* src;
    if      (by < 8)  src = Wg + (size_t)by * DIM * HID;
    else if (by < 16) src = Wu + (size_t)(by - 8) * DIM * HID;
    else if (by == 16) src = sg;
    else               src = su;
    size_t base = (size_t)blockIdx.x * 1024 + threadIdx.x;
    #pragma unroll
    for (int j = 0; j < 4; j++) convert_one(src, m, base + j * 256);
}

// down matrices (9): indices 16..23, 26
__global__ void convert_w_d_kernel(
    const float* __restrict__ Wd, const float* __restrict__ sd)
{
    int by = blockIdx.y;
    int m = (by < 8) ? 16 + by : 26;
    const float* src = (by < 8) ? Wd + (size_t)by * DIM * HID : sd;
    size_t base = (size_t)blockIdx.x * 1024 + threadIdx.x;
    #pragma unroll
    for (int j = 0; j < 4; j++) convert_one(src, m, base + j * 256);
}

// router: 1 token per warp, 512 blocks; also emits fp16 X (fused convert_x)
__global__ __launch_bounds__(256, 4) void router_kernel(
    const float* __restrict__ X, const float* __restrict__ Wr,
    const float* __restrict__ loop_table, const int* __restrict__ loop_idx)
{
    __shared__ float4 sW[NE][256];
    __shared__ float s_bias[NE];
    const int tid = threadIdx.x, warp = tid >> 5, lane = tid & 31;

    for (int i = tid; i < NE * 256; i += 256) {
        int e = i >> 8, k4 = i & 255;
        sW[e][k4] = make_float4(Wr[(size_t)(k4 * 4 + 0) * NE + e],
                                Wr[(size_t)(k4 * 4 + 1) * NE + e],
                                Wr[(size_t)(k4 * 4 + 2) * NE + e],
                                Wr[(size_t)(k4 * 4 + 3) * NE + e]);
    }
    const float* le = loop_table + (size_t)loop_idx[0] * DIM;
    float b = 0.f;
    for (int d = lane; d < DIM; d += 32)
        b += le[d] * Wr[(size_t)(DIM + d) * NE + warp];
    #pragma unroll
    for (int o = 16; o; o >>= 1) b += __shfl_xor_sync(~0u, b, o);
    if (lane == 0) s_bias[warp] = b;
    __syncthreads();

    const int t = blockIdx.x * 8 + warp;
    const float4* xr = (const float4*)(X + (size_t)t * DIM);
    uint2* xo = (uint2*)(g_Xf + (size_t)t * DIM);
    float acc[NE];
    #pragma unroll
    for (int e = 0; e < NE; e++) acc[e] = 0.f;
    #pragma unroll 1
    for (int i = 0; i < 8; i++) {
        float4 xv = xr[lane + 32 * i];
        // fused convert_x: write fp16 copy (identical to old convert_x_kernel)
        __half2 ha = __floats2half2_rn(xv.x, xv.y);
        __half2 hb = __floats2half2_rn(xv.z, xv.w);
        xo[lane + 32 * i] = make_uint2(*(uint32_t*)&ha, *(uint32_t*)&hb);
        const float4* swp = &sW[0][lane + 32 * i];
        #pragma unroll
        for (int e = 0; e < NE; e++) {
            float4 w = swp[e * 256];
            acc[e] += xv.x * w.x + xv.y * w.y + xv.z * w.z + xv.w * w.w;
        }
    }
    #pragma unroll
    for (int e = 0; e < NE; e++)
        #pragma unroll
        for (int o = 16; o; o >>= 1) acc[e] += __shfl_xor_sync(~0u, acc[e], o);

    if (lane == 0) {
        float p[NE];
        #pragma unroll
        for (int e = 0; e < NE; e++)
            p[e] = 1.f / (1.f + expf(-(acc[e] + s_bias[e])));
        int i0 = 0; float v0 = p[0];
        #pragma unroll
        for (int e = 1; e < NE; e++) if (p[e] > v0) { v0 = p[e]; i0 = e; }
        int i1 = -1; float v1 = -1e30f;
        #pragma unroll
        for (int e = 0; e < NE; e++) {
            if (e == i0) continue;
            if (p[e] > v1) { v1 = p[e]; i1 = e; }
        }
        g_top_e[t * 2 + 0] = i0;  g_top_e[t * 2 + 1] = i1;
        g_top_w[t * 2 + 0] = v0;  g_top_w[t * 2 + 1] = v1;
    }
}

__global__ void dispatch_kernel() {
    int t = blockIdx.x * blockDim.x + threadIdx.x;
    if (t >= N_TOK) return;
    #pragma unroll
    for (int k = 0; k < 2; k++) {
        int e = g_top_e[t * 2 + k];
        int pos = atomicAdd(&g_cnt[e], 1);
        g_assign_token[e * N_TOK + pos] = t;
        g_assign_slot [e * N_TOK + pos] = k;
    }
}

// ---------------- GEMM1: X @ {Wg,Wu}[e], fused SiLU -> fp16 h ---------------
// Block 128m x 64n, BK=32 per stage, 3-stage. A pitch 80B, B pitch 144B.
#define S1_A  0u
#define S1_G  10240u
#define S1_U  14848u
#define S1_STG 19456u

__global__ __launch_bounds__(256) void gemm1_kernel() {
    extern __shared__ char sm[];
    __shared__ int s_token[128];

    const int e   = blockIdx.z;
    const int cnt = g_cnt[e];
    const int m0  = blockIdx.y * 128;
    if (m0 >= cnt) return;
    const int n0  = blockIdx.x * 64;
    const int tid = threadIdx.x, wid = tid >> 5, lane = tid & 31;

    const int ig = (e < NE) ? e : 24;
    const int iu = (e < NE) ? 8 + e : 25;

    if (tid < 128) {
        int r = m0 + tid;
        s_token[tid] = (e < NE) ? ((r < cnt) ? g_assign_token[e * N_TOK + r] : 0) : r;
    }
    __syncthreads();
    const uint32_t sb = smem_u32(sm);

    const char* wg = (const char*)(g_Wf + (size_t)ig * DIM * HID);
    const char* wu = (const char*)(g_Wf + (size_t)iu * DIM * HID);

    const int ar0 = tid >> 2, ac = (tid & 3) * 16;
    const char* aSrc0 = (const char*)(g_Xf + (size_t)s_token[ar0] * DIM) + ac;
    const char* aSrc1 = (const char*)(g_Xf + (size_t)s_token[64 + ar0] * DIM) + ac;
    const uint32_t aDst0 = sb + S1_A + ar0 * 80 + ac;
    const uint32_t aDst1 = sb + S1_A + (64 + ar0) * 80 + ac;
    const int brw = tid >> 3, bcc = (tid & 7) * 16;
    const char* gSrc = wg + (size_t)brw * HID * 2 + n0 * 2 + bcc;
    const char* uSrc = wu + (size_t)brw * HID * 2 + n0 * 2 + bcc;
    const uint32_t gDst = sb + S1_G + brw * 144 + bcc;
    const uint32_t uDst = sb + S1_U + brw * 144 + bcc;

#define G_LOAD(k0, buf) do { \
        uint32_t _o = (uint32_t)(buf) * S1_STG; \
        size_t _ab = (size_t)(k0) * 2; \
        size_t _bb = (size_t)(k0) * HID * 2; \
        CP_ASYNC16(aDst0 + _o, aSrc0 + _ab); \
        CP_ASYNC16(aDst1 + _o, aSrc1 + _ab); \
        CP_ASYNC16(gDst + _o, gSrc + _bb); \
        CP_ASYNC16(uDst + _o, uSrc + _bb); \
        CP_COMMIT(); } while (0)

    const int wm = (wid & 3) * 32, wn = (wid >> 2) * 32;
    const int am = (lane & 7) + ((lane >> 3) & 1) * 8;
    const uint32_t ako = (lane >> 4) * 16;
    const uint32_t aB = sb + S1_A + (wm + am) * 80 + ako;
    const int bk = lane & 15;
    const uint32_t bG = sb + S1_G + bk * 144 + wn * 2;
    const uint32_t bU = sb + S1_U + bk * 144 + wn * 2;

    float accG[2][4][4], accU[2][4][4];
    #pragma unroll
    for (int i = 0; i < 2; i++)
        #pragma unroll
        for (int j = 0; j < 4; j++)
            #pragma unroll
            for (int q = 0; q < 4; q++) { accG[i][j][q] = 0.f; accU[i][j][q] = 0.f; }

    G_LOAD(0, 0);
    G_LOAD(32, 1);
    CP_WAIT(1); __syncthreads();

    int cur = 0;
    for (int s = 0; s < 32; s++) {
        int ldb = cur + 2; if (ldb >= 3) ldb -= 3;
        if (s + 2 < 32) G_LOAD((s + 2) * 32, ldb);

        const uint32_t off = (uint32_t)cur * S1_STG;
        #pragma unroll
        for (int ks = 0; ks < 2; ks++) {
            uint32_t a[2][4], bg[4][2], bu[4][2];
            #pragma unroll
            for (int i = 0; i < 2; i++)
                ldsm_x4(a[i], aB + off + ks * 32 + i * 1280);
            #pragma unroll
            for (int j = 0; j < 4; j++) {
                ldsm_x2_t(bg[j], bG + off + ks * 2304 + j * 16);
                ldsm_x2_t(bu[j], bU + off + ks * 2304 + j * 16);
            }
            #pragma unroll
            for (int i = 0; i < 2; i++)
                #pragma unroll
                for (int j = 0; j < 4; j++) {
                    mma_f16(accG[i][j], a[i], bg[j]);
                    mma_f16(accU[i][j], a[i], bu[j]);
                }
        }
        if (s + 2 < 32) CP_WAIT(1); else CP_WAIT(0);
        __syncthreads();
        cur++; if (cur == 3) cur = 0;
    }

    const int qr = lane >> 2, r4 = lane & 3;
    #pragma unroll
    for (int i = 0; i < 2; i++) {
        const int lr0 = wm + i * 16 + qr, lr1 = lr0 + 8;
        const bool ok0 = (m0 + lr0) < cnt, ok1 = (m0 + lr1) < cnt;
        __half* d0 = g_Hf + ((size_t)e * N_TOK + m0 + lr0) * HID + n0;
        __half* d1 = g_Hf + ((size_t)e * N_TOK + m0 + lr1) * HID + n0;
        #pragma unroll
        for (int j = 0; j < 4; j++) {
            const int col = wn + j * 8 + r4 * 2;
            float h00 = silu(accG[i][j][0]) * accU[i][j][0];
            float h01 = silu(accG[i][j][1]) * accU[i][j][1];
            float h10 = silu(accG[i][j][2]) * accU[i][j][2];
            float h11 = silu(accG[i][j][3]) * accU[i][j][3];
            if (ok0) *(__half2*)(d0 + col) = __floats2half2_rn(h00, h01);
            if (ok1) *(__half2*)(d1 + col) = __floats2half2_rn(h10, h11);
        }
    }
#undef G_LOAD
}

// ---------------- GEMM2: h @ Wd[e] -> scattered fp32 rbuf -------------------
// Block 128m x 64n, BK=32 per stage, 3-stage.
#define S2_A  0u
#define S2_B  10240u
#define S2_STG 14848u

__global__ __launch_bounds__(256) void gemm2_kernel() {
    extern __shared__ char sm[];
    __shared__ int s_dst[128];

    const int e   = blockIdx.z;
    const int cnt = g_cnt[e];
    const int m0  = blockIdx.y * 128;
    if (m0 >= cnt) return;
    const int n0  = blockIdx.x * 64;
    const int tid = threadIdx.x, wid = tid >> 5, lane = tid & 31;

    const int id = (e < NE) ? 16 + e : 26;

    if (tid < 128) {
        int r = m0 + tid, dst = 0;
        if (r < cnt) {
            if (e < NE)
                dst = g_assign_slot[e * N_TOK + r] * N_TOK + g_assign_token[e * N_TOK + r];
            else
                dst = 2 * N_TOK + r;
        }
        s_dst[tid] = dst;
    }
    __syncthreads();
    const uint32_t sb = smem_u32(sm);

    const char* wd = (const char*)(g_Wf + (size_t)id * DIM * HID);

    const int ar0 = tid >> 2, ac = (tid & 3) * 16;
    const char* aSrc0 = (const char*)(g_Hf + ((size_t)e * N_TOK + m0 + ar0) * HID) + ac;
    const char* aSrc1 = (const char*)(g_Hf + ((size_t)e * N_TOK + m0 + 64 + ar0) * HID) + ac;
    const uint32_t aDst0 = sb + S2_A + ar0 * 80 + ac;
    const uint32_t aDst1 = sb + S2_A + (64 + ar0) * 80 + ac;
    const int brw = tid >> 3, bcc = (tid & 7) * 16;
    const char* bSrc = wd + (size_t)brw * DIM * 2 + n0 * 2 + bcc;
    const uint32_t bDst = sb + S2_B + brw * 144 + bcc;

#define G_LOAD(k0, buf) do { \
        uint32_t _o = (uint32_t)(buf) * S2_STG; \
        size_t _ab = (size_t)(k0) * 2; \
        size_t _bb = (size_t)(k0) * DIM * 2; \
        CP_ASYNC16(aDst0 + _o, aSrc0 + _ab); \
        CP_ASYNC16(aDst1 + _o, aSrc1 + _ab); \
        CP_ASYNC16(bDst + _o, bSrc + _bb); \
        CP_COMMIT(); } while (0)

    const int wm = (wid & 3) * 32, wn = (wid >> 2) * 32;
    const int am = (lane & 7) + ((lane >> 3) & 1) * 8;
    const uint32_t ako = (lane >> 4) * 16;
    const uint32_t aB = sb + S2_A + (wm + am) * 80 + ako;
    const int bk = lane & 15;
    const uint32_t bB = sb + S2_B + bk * 144 + wn * 2;

    float acc[2][4][4];
    #pragma unroll
    for (int i = 0; i < 2; i++)
        #pragma unroll
        for (int j = 0; j < 4; j++)
            #pragma unroll
            for (int q = 0; q < 4; q++) acc[i][j][q] = 0.f;

    G_LOAD(0, 0);
    G_LOAD(32, 1);
    CP_WAIT(1); __syncthreads();

    int cur = 0;
    for (int s = 0; s < 32; s++) {
        int ldb = cur + 2; if (ldb >= 3) ldb -= 3;
        if (s + 2 < 32) G_LOAD((s + 2) * 32, ldb);

        const uint32_t off = (uint32_t)cur * S2_STG;
        #pragma unroll
        for (int ks = 0; ks < 2; ks++) {
            uint32_t a[2][4], b[4][2];
            #pragma unroll
            for (int i = 0; i < 2; i++)
                ldsm_x4(a[i], aB + off + ks * 32 + i * 1280);
            #pragma unroll
            for (int j = 0; j < 4; j++)
                ldsm_x2_t(b[j], bB + off + ks * 2304 + j * 16);
            #pragma unroll
            for (int i = 0; i < 2; i++)
                #pragma unroll
                for (int j = 0; j < 4; j++)
                    mma_f16(acc[i][j], a[i], b[j]);
        }
        if (s + 2 < 32) CP_WAIT(1); else CP_WAIT(0);
        __syncthreads();
        cur++; if (cur == 3) cur = 0;
    }

    const int qr = lane >> 2, r4 = lane & 3;
    #pragma unroll
    for (int i = 0; i < 2; i++) {
        const int lr0 = wm + i * 16 + qr, lr1 = lr0 + 8;
        const bool ok0 = (m0 + lr0) < cnt, ok1 = (m0 + lr1) < cnt;
        float* d0 = g_rbuf + (size_t)s_dst[lr0] * DIM + n0;
        float* d1 = g_rbuf + (size_t)s_dst[lr1] * DIM + n0;
        #pragma unroll
        for (int j = 0; j < 4; j++) {
            const int col = wn + j * 8 + r4 * 2;
            if (ok0) *(float2*)(d0 + col) = make_float2(acc[i][j][0], acc[i][j][1]);
            if (ok1) *(float2*)(d1 + col) = make_float2(acc[i][j][2], acc[i][j][3]);
        }
    }
#undef G_LOAD
}

// ---------------- combine ---------------------------------------------------
__global__ void combine_kernel(float* __restrict__ out) {
    int i4 = blockIdx.x * 256 + threadIdx.x;
    int t  = i4 >> 8;
    float w0 = g_top_w[2 * t], w1 = g_top_w[2 * t + 1];
    float4 a = ((const float4*)g_rbuf)[i4];
    float4 b = ((const float4*)g_rbuf)[(size_t)(N_TOK * DIM / 4) + i4];
    float4 c = ((const float4*)g_rbuf)[(size_t)(2 * N_TOK * DIM / 4) + i4];
    float4 o;
    o.x = c.x + w0 * a.x + w1 * b.x;
    o.y = c.y + w0 * a.y + w1 * b.y;
    o.z = c.z + w0 * a.z + w1 * b.z;
    o.w = c.w + w0 * a.w + w1 * b.w;
    ((float4*)out)[i4] = o;
}

// ---------------- launch ----------------------------------------------------
extern "C" void kernel_launch(void* const* d_in, const int* in_sizes, int n_in,
                              void* d_out, int out_size)
{
    const float* x  = (const float*)d_in[0];
    const float* sg = (const float*)d_in[1];
    const float* su = (const float*)d_in[2];
    const float* sd = (const float*)d_in[3];
    const float* Wg = (const float*)d_in[4];
    const float* Wu = (const float*)d_in[5];
    const float* Wd = (const float*)d_in[6];
    const float* Wr = (const float*)d_in[7];
    const float* lt = (const float*)d_in[8];
    const int*   li = (const int*)d_in[9];
    float* out = (float*)d_out;
    (void)in_sizes; (void)n_in; (void)out_size;

    static cudaStream_t s2 = nullptr;
    static cudaEvent_t evFork = nullptr, evGU = nullptr, evD = nullptr;
    static int init_done = 0;
    if (!init_done) {
        cudaFuncSetAttribute(gemm1_kernel, cudaFuncAttributeMaxDynamicSharedMemorySize, 3 * S1_STG);
        cudaFuncSetAttribute(gemm2_kernel, cudaFuncAttributeMaxDynamicSharedMemorySize, 3 * S2_STG);
        cudaStreamCreateWithFlags(&s2, cudaStreamNonBlocking);
        cudaEventCreateWithFlags(&evFork, cudaEventDisableTiming);
        cudaEventCreateWithFlags(&evGU, cudaEventDisableTiming);
        cudaEventCreateWithFlags(&evD, cudaEventDisableTiming);
        init_done = 1;
    }

    // R12 schedule: main = routing chain (now also produces fp16 X);
    // s2 = weight conversion only.
    cudaEventRecord(evFork, 0);
    cudaStreamWaitEvent(s2, evFork, 0);

    zero_kernel<<<1, 32>>>();
    router_kernel<<<N_TOK / 8, 256>>>(x, Wr, lt, li);
    dispatch_kernel<<<N_TOK / 256, 256>>>();

    convert_w_gu_kernel<<<dim3((DIM * HID / 4) / 1024, 18), 256, 0, s2>>>(Wg, Wu, sg, su);
    cudaEventRecord(evGU, s2);
    convert_w_d_kernel<<<dim3((DIM * HID / 4) / 1024, 9), 256, 0, s2>>>(Wd, sd);
    cudaEventRecord(evD, s2);

    cudaStreamWaitEvent(0, evGU, 0);
    gemm1_kernel<<<dim3(16, 32, NSEG), 256, 3 * S1_STG>>>();
    cudaStreamWaitEvent(0, evD, 0);
    gemm2_kernel<<<dim3(16, 32, NSEG), 256, 3 * S2_STG>>>();
    combine_kernel<<<(N_TOK * (DIM / 4)) / 256, 256>>>(out);
}

// round 17
// speedup vs baseline: 1.3668x; 1.0070x over previous
#include <cuda_runtime.h>
#include <cuda_fp16.h>
#include <cstdint>

#define N_TOK 4096
#define DIM   1024
#define HID   1024
#define NE    8
#define NSEG  9

// ---------------- scratch ---------------------------------------------------
__device__ int   g_cnt[NSEG];
__device__ int   g_assign_token[NE * N_TOK];
__device__ int   g_assign_slot [NE * N_TOK];
__device__ float g_top_w[N_TOK * 2];
__device__ __half g_Xf[(size_t)N_TOK * DIM];
// 27 matrices [k][n]: Wg[0..7], Wu[8..15], Wd[16..23], sg=24, su=25, sd=26
__device__ __half g_Wf[(size_t)27 * DIM * HID];
__device__ __half g_Hf[(size_t)NSEG * N_TOK * HID];
__device__ float g_rbuf[(size_t)3 * N_TOK * DIM];

// ---------------- helpers ---------------------------------------------------
__device__ __forceinline__ uint32_t smem_u32(const void* p) {
    uint32_t a;
    asm("{ .reg .u64 t; cvta.to.shared.u64 t, %1; cvt.u32.u64 %0, t; }"
        : "=r"(a) : "l"(p));
    return a;
}
#define CP_ASYNC16(dst, src) \
    asm volatile("cp.async.cg.shared.global [%0], [%1], 16;" :: "r"(dst), "l"(src))
#define CP_COMMIT() asm volatile("cp.async.commit_group;" ::: "memory")
#define CP_WAIT(n)  asm volatile("cp.async.wait_group %0;" :: "n"(n) : "memory")

__device__ __forceinline__ void ldsm_x4(uint32_t* r, uint32_t addr) {
    asm volatile("ldmatrix.sync.aligned.m8n8.x4.shared.b16 {%0,%1,%2,%3}, [%4];"
        : "=r"(r[0]), "=r"(r[1]), "=r"(r[2]), "=r"(r[3]) : "r"(addr));
}
__device__ __forceinline__ void ldsm_x2_t(uint32_t* r, uint32_t addr) {
    asm volatile("ldmatrix.sync.aligned.m8n8.x2.trans.shared.b16 {%0,%1}, [%2];"
        : "=r"(r[0]), "=r"(r[1]) : "r"(addr));
}
__device__ __forceinline__ void mma_f16(float* d, const uint32_t* a, const uint32_t* b) {
    asm volatile(
        "mma.sync.aligned.m16n8k16.row.col.f32.f16.f16.f32 "
        "{%0,%1,%2,%3}, {%4,%5,%6,%7}, {%8,%9}, {%0,%1,%2,%3};"
        : "+f"(d[0]), "+f"(d[1]), "+f"(d[2]), "+f"(d[3])
        : "r"(a[0]), "r"(a[1]), "r"(a[2]), "r"(a[3]), "r"(b[0]), "r"(b[1]));
}
__device__ __forceinline__ float silu(float g) { return g / (1.f + __expf(-g)); }

__device__ __forceinline__ void convert_one(const float* __restrict__ src,
                                            int m, size_t i4)
{
    float4 v = ((const float4*)src)[i4];
    __half2 a = __floats2half2_rn(v.x, v.y);
    __half2 b = __floats2half2_rn(v.z, v.w);
    size_t o = (size_t)m * (DIM * HID / 4) + i4;
    ((uint2*)g_Wf)[o] = make_uint2(*(uint32_t*)&a, *(uint32_t*)&b);
}

// ---------------- small kernels ---------------------------------------------
__global__ void zero_kernel() {
    int t = threadIdx.x;
    if (t < NE) g_cnt[t] = 0;
    if (t == NE) g_cnt[NE] = N_TOK;
}

// gate/up matrices (18): indices 0..15, 24, 25
__global__ void convert_w_gu_kernel(
    const float* __restrict__ Wg, const float* __restrict__ Wu,
    const float* __restrict__ sg, const float* __restrict__ su)
{
    int by = blockIdx.y;
    int m = (by < 16) ? by : 24 + (by - 16);
    const float* src;
    if      (by < 8)  src = Wg + (size_t)by * DIM * HID;
    else if (by < 16) src = Wu + (size_t)(by - 8) * DIM * HID;
    else if (by == 16) src = sg;
    else               src = su;
    size_t base = (size_t)blockIdx.x * 1024 + threadIdx.x;
    #pragma unroll
    for (int j = 0; j < 4; j++) convert_one(src, m, base + j * 256);
}

// down matrices (9): indices 16..23, 26
__global__ void convert_w_d_kernel(
    const float* __restrict__ Wd, const float* __restrict__ sd)
{
    int by = blockIdx.y;
    int m = (by < 8) ? 16 + by : 26;
    const float* src = (by < 8) ? Wd + (size_t)by * DIM * HID : sd;
    size_t base = (size_t)blockIdx.x * 1024 + threadIdx.x;
    #pragma unroll
    for (int j = 0; j < 4; j++) convert_one(src, m, base + j * 256);
}

// router: 1 token per warp; emits fp16 X AND does dispatch (fused).
__global__ __launch_bounds__(256, 4) void router_kernel(
    const float* __restrict__ X, const float* __restrict__ Wr,
    const float* __restrict__ loop_table, const int* __restrict__ loop_idx)
{
    __shared__ float4 sW[NE][256];
    __shared__ float s_bias[NE];
    const int tid = threadIdx.x, warp = tid >> 5, lane = tid & 31;

    for (int i = tid; i < NE * 256; i += 256) {
        int e = i >> 8, k4 = i & 255;
        sW[e][k4] = make_float4(Wr[(size_t)(k4 * 4 + 0) * NE + e],
                                Wr[(size_t)(k4 * 4 + 1) * NE + e],
                                Wr[(size_t)(k4 * 4 + 2) * NE + e],
                                Wr[(size_t)(k4 * 4 + 3) * NE + e]);
    }
    const float* le = loop_table + (size_t)loop_idx[0] * DIM;
    float b = 0.f;
    for (int d = lane; d < DIM; d += 32)
        b += le[d] * Wr[(size_t)(DIM + d) * NE + warp];
    #pragma unroll
    for (int o = 16; o; o >>= 1) b += __shfl_xor_sync(~0u, b, o);
    if (lane == 0) s_bias[warp] = b;
    __syncthreads();

    const int t = blockIdx.x * 8 + warp;
    const float4* xr = (const float4*)(X + (size_t)t * DIM);
    uint2* xo = (uint2*)(g_Xf + (size_t)t * DIM);
    float acc[NE];
    #pragma unroll
    for (int e = 0; e < NE; e++) acc[e] = 0.f;
    #pragma unroll 1
    for (int i = 0; i < 8; i++) {
        float4 xv = xr[lane + 32 * i];
        __half2 ha = __floats2half2_rn(xv.x, xv.y);
        __half2 hb = __floats2half2_rn(xv.z, xv.w);
        xo[lane + 32 * i] = make_uint2(*(uint32_t*)&ha, *(uint32_t*)&hb);
        const float4* swp = &sW[0][lane + 32 * i];
        #pragma unroll
        for (int e = 0; e < NE; e++) {
            float4 w = swp[e * 256];
            acc[e] += xv.x * w.x + xv.y * w.y + xv.z * w.z + xv.w * w.w;
        }
    }
    #pragma unroll
    for (int e = 0; e < NE; e++)
        #pragma unroll
        for (int o = 16; o; o >>= 1) acc[e] += __shfl_xor_sync(~0u, acc[e], o);

    if (lane == 0) {
        float p[NE];
        #pragma unroll
        for (int e = 0; e < NE; e++)
            p[e] = 1.f / (1.f + expf(-(acc[e] + s_bias[e])));
        int i0 = 0; float v0 = p[0];
        #pragma unroll
        for (int e = 1; e < NE; e++) if (p[e] > v0) { v0 = p[e]; i0 = e; }
        int i1 = -1; float v1 = -1e30f;
        #pragma unroll
        for (int e = 0; e < NE; e++) {
            if (e == i0) continue;
            if (p[e] > v1) { v1 = p[e]; i1 = e; }
        }
        g_top_w[t * 2 + 0] = v0;  g_top_w[t * 2 + 1] = v1;
        // fused dispatch
        int p0 = atomicAdd(&g_cnt[i0], 1);
        g_assign_token[i0 * N_TOK + p0] = t;
        g_assign_slot [i0 * N_TOK + p0] = 0;
        int p1 = atomicAdd(&g_cnt[i1], 1);
        g_assign_token[i1 * N_TOK + p1] = t;
        g_assign_slot [i1 * N_TOK + p1] = 1;
    }
}

// ---------------- GEMM1: X @ {Wg,Wu}[e], fused SiLU -> fp16 h ---------------
// Block 128m x 64n, BK=32 per stage, 3-stage. A pitch 80B, B pitch 144B.
#define S1_A  0u
#define S1_G  10240u
#define S1_U  14848u
#define S1_STG 19456u

__global__ __launch_bounds__(256) void gemm1_kernel() {
    extern __shared__ char sm[];
    __shared__ int s_token[128];

    const int e   = blockIdx.z;
    const int cnt = g_cnt[e];
    const int m0  = blockIdx.y * 128;
    if (m0 >= cnt) return;
    const int n0  = blockIdx.x * 64;
    const int tid = threadIdx.x, wid = tid >> 5, lane = tid & 31;

    const int ig = (e < NE) ? e : 24;
    const int iu = (e < NE) ? 8 + e : 25;

    if (tid < 128) {
        int r = m0 + tid;
        s_token[tid] = (e < NE) ? ((r < cnt) ? g_assign_token[e * N_TOK + r] : 0) : r;
    }
    __syncthreads();
    const uint32_t sb = smem_u32(sm);

    const char* wg = (const char*)(g_Wf + (size_t)ig * DIM * HID);
    const char* wu = (const char*)(g_Wf + (size_t)iu * DIM * HID);

    const int ar0 = tid >> 2, ac = (tid & 3) * 16;
    const char* aSrc0 = (const char*)(g_Xf + (size_t)s_token[ar0] * DIM) + ac;
    const char* aSrc1 = (const char*)(g_Xf + (size_t)s_token[64 + ar0] * DIM) + ac;
    const uint32_t aDst0 = sb + S1_A + ar0 * 80 + ac;
    const uint32_t aDst1 = sb + S1_A + (64 + ar0) * 80 + ac;
    const int brw = tid >> 3, bcc = (tid & 7) * 16;
    const char* gSrc = wg + (size_t)brw * HID * 2 + n0 * 2 + bcc;
    const char* uSrc = wu + (size_t)brw * HID * 2 + n0 * 2 + bcc;
    const uint32_t gDst = sb + S1_G + brw * 144 + bcc;
    const uint32_t uDst = sb + S1_U + brw * 144 + bcc;

#define G_LOAD(k0, buf) do { \
        uint32_t _o = (uint32_t)(buf) * S1_STG; \
        size_t _ab = (size_t)(k0) * 2; \
        size_t _bb = (size_t)(k0) * HID * 2; \
        CP_ASYNC16(aDst0 + _o, aSrc0 + _ab); \
        CP_ASYNC16(aDst1 + _o, aSrc1 + _ab); \
        CP_ASYNC16(gDst + _o, gSrc + _bb); \
        CP_ASYNC16(uDst + _o, uSrc + _bb); \
        CP_COMMIT(); } while (0)

    const int wm = (wid & 3) * 32, wn = (wid >> 2) * 32;
    const int am = (lane & 7) + ((lane >> 3) & 1) * 8;
    const uint32_t ako = (lane >> 4) * 16;
    const uint32_t aB = sb + S1_A + (wm + am) * 80 + ako;
    const int bk = lane & 15;
    const uint32_t bG = sb + S1_G + bk * 144 + wn * 2;
    const uint32_t bU = sb + S1_U + bk * 144 + wn * 2;

    float accG[2][4][4], accU[2][4][4];
    #pragma unroll
    for (int i = 0; i < 2; i++)
        #pragma unroll
        for (int j = 0; j < 4; j++)
            #pragma unroll
            for (int q = 0; q < 4; q++) { accG[i][j][q] = 0.f; accU[i][j][q] = 0.f; }

    G_LOAD(0, 0);
    G_LOAD(32, 1);
    CP_WAIT(1); __syncthreads();

    int cur = 0;
    for (int s = 0; s < 32; s++) {
        int ldb = cur + 2; if (ldb >= 3) ldb -= 3;
        if (s + 2 < 32) G_LOAD((s + 2) * 32, ldb);

        const uint32_t off = (uint32_t)cur * S1_STG;
        #pragma unroll
        for (int ks = 0; ks < 2; ks++) {
            uint32_t a[2][4], bg[4][2], bu[4][2];
            #pragma unroll
            for (int i = 0; i < 2; i++)
                ldsm_x4(a[i], aB + off + ks * 32 + i * 1280);
            #pragma unroll
            for (int j = 0; j < 4; j++) {
                ldsm_x2_t(bg[j], bG + off + ks * 2304 + j * 16);
                ldsm_x2_t(bu[j], bU + off + ks * 2304 + j * 16);
            }
            #pragma unroll
            for (int i = 0; i < 2; i++)
                #pragma unroll
                for (int j = 0; j < 4; j++) {
                    mma_f16(accG[i][j], a[i], bg[j]);
                    mma_f16(accU[i][j], a[i], bu[j]);
                }
        }
        if (s + 2 < 32) CP_WAIT(1); else CP_WAIT(0);
        __syncthreads();
        cur++; if (cur == 3) cur = 0;
    }

    const int qr = lane >> 2, r4 = lane & 3;
    #pragma unroll
    for (int i = 0; i < 2; i++) {
        const int lr0 = wm + i * 16 + qr, lr1 = lr0 + 8;
        const bool ok0 = (m0 + lr0) < cnt, ok1 = (m0 + lr1) < cnt;
        __half* d0 = g_Hf + ((size_t)e * N_TOK + m0 + lr0) * HID + n0;
        __half* d1 = g_Hf + ((size_t)e * N_TOK + m0 + lr1) * HID + n0;
        #pragma unroll
        for (int j = 0; j < 4; j++) {
            const int col = wn + j * 8 + r4 * 2;
            float h00 = silu(accG[i][j][0]) * accU[i][j][0];
            float h01 = silu(accG[i][j][1]) * accU[i][j][1];
            float h10 = silu(accG[i][j][2]) * accU[i][j][2];
            float h11 = silu(accG[i][j][3]) * accU[i][j][3];
            if (ok0) *(__half2*)(d0 + col) = __floats2half2_rn(h00, h01);
            if (ok1) *(__half2*)(d1 + col) = __floats2half2_rn(h10, h11);
        }
    }
#undef G_LOAD
}

// ---------------- GEMM2: h @ Wd[e] -> scattered fp32 rbuf -------------------
// Block 128m x 64n, BK=32 per stage, 3-stage.
#define S2_A  0u
#define S2_B  10240u
#define S2_STG 14848u

__global__ __launch_bounds__(256) void gemm2_kernel() {
    extern __shared__ char sm[];
    __shared__ int s_dst[128];

    const int e   = blockIdx.z;
    const int cnt = g_cnt[e];
    const int m0  = blockIdx.y * 128;
    if (m0 >= cnt) return;
    const int n0  = blockIdx.x * 64;
    const int tid = threadIdx.x, wid = tid >> 5, lane = tid & 31;

    const int id = (e < NE) ? 16 + e : 26;

    if (tid < 128) {
        int r = m0 + tid, dst = 0;
        if (r < cnt) {
            if (e < NE)
                dst = g_assign_slot[e * N_TOK + r] * N_TOK + g_assign_token[e * N_TOK + r];
            else
                dst = 2 * N_TOK + r;
        }
        s_dst[tid] = dst;
    }
    __syncthreads();
    const uint32_t sb = smem_u32(sm);

    const char* wd = (const char*)(g_Wf + (size_t)id * DIM * HID);

    const int ar0 = tid >> 2, ac = (tid & 3) * 16;
    const char* aSrc0 = (const char*)(g_Hf + ((size_t)e * N_TOK + m0 + ar0) * HID) + ac;
    const char* aSrc1 = (const char*)(g_Hf + ((size_t)e * N_TOK + m0 + 64 + ar0) * HID) + ac;
    const uint32_t aDst0 = sb + S2_A + ar0 * 80 + ac;
    const uint32_t aDst1 = sb + S2_A + (64 + ar0) * 80 + ac;
    const int brw = tid >> 3, bcc = (tid & 7) * 16;
    const char* bSrc = wd + (size_t)brw * DIM * 2 + n0 * 2 + bcc;
    const uint32_t bDst = sb + S2_B + brw * 144 + bcc;

#define G_LOAD(k0, buf) do { \
        uint32_t _o = (uint32_t)(buf) * S2_STG; \
        size_t _ab = (size_t)(k0) * 2; \
        size_t _bb = (size_t)(k0) * DIM * 2; \
        CP_ASYNC16(aDst0 + _o, aSrc0 + _ab); \
        CP_ASYNC16(aDst1 + _o, aSrc1 + _ab); \
        CP_ASYNC16(bDst + _o, bSrc + _bb); \
        CP_COMMIT(); } while (0)

    const int wm = (wid & 3) * 32, wn = (wid >> 2) * 32;
    const int am = (lane & 7) + ((lane >> 3) & 1) * 8;
    const uint32_t ako = (lane >> 4) * 16;
    const uint32_t aB = sb + S2_A + (wm + am) * 80 + ako;
    const int bk = lane & 15;
    const uint32_t bB = sb + S2_B + bk * 144 + wn * 2;

    float acc[2][4][4];
    #pragma unroll
    for (int i = 0; i < 2; i++)
        #pragma unroll
        for (int j = 0; j < 4; j++)
            #pragma unroll
            for (int q = 0; q < 4; q++) acc[i][j][q] = 0.f;

    G_LOAD(0, 0);
    G_LOAD(32, 1);
    CP_WAIT(1); __syncthreads();

    int cur = 0;
    for (int s = 0; s < 32; s++) {
        int ldb = cur + 2; if (ldb >= 3) ldb -= 3;
        if (s + 2 < 32) G_LOAD((s + 2) * 32, ldb);

        const uint32_t off = (uint32_t)cur * S2_STG;
        #pragma unroll
        for (int ks = 0; ks < 2; ks++) {
            uint32_t a[2][4], b[4][2];
            #pragma unroll
            for (int i = 0; i < 2; i++)
                ldsm_x4(a[i], aB + off + ks * 32 + i * 1280);
            #pragma unroll
            for (int j = 0; j < 4; j++)
                ldsm_x2_t(b[j], bB + off + ks * 2304 + j * 16);
            #pragma unroll
            for (int i = 0; i < 2; i++)
                #pragma unroll
                for (int j = 0; j < 4; j++)
                    mma_f16(acc[i][j], a[i], b[j]);
        }
        if (s + 2 < 32) CP_WAIT(1); else CP_WAIT(0);
        __syncthreads();
        cur++; if (cur == 3) cur = 0;
    }

    const int qr = lane >> 2, r4 = lane & 3;
    #pragma unroll
    for (int i = 0; i < 2; i++) {
        const int lr0 = wm + i * 16 + qr, lr1 = lr0 + 8;
        const bool ok0 = (m0 + lr0) < cnt, ok1 = (m0 + lr1) < cnt;
        float* d0 = g_rbuf + (size_t)s_dst[lr0] * DIM + n0;
        float* d1 = g_rbuf + (size_t)s_dst[lr1] * DIM + n0;
        #pragma unroll
        for (int j = 0; j < 4; j++) {
            const int col = wn + j * 8 + r4 * 2;
            if (ok0) *(float2*)(d0 + col) = make_float2(acc[i][j][0], acc[i][j][1]);
            if (ok1) *(float2*)(d1 + col) = make_float2(acc[i][j][2], acc[i][j][3]);
        }
    }
#undef G_LOAD
}

// ---------------- combine (4x ILP) ------------------------------------------
__global__ void combine_kernel(float* __restrict__ out) {
    const size_t base = (size_t)blockIdx.x * 1024 + threadIdx.x;
    const size_t off1 = (size_t)(N_TOK * DIM / 4);
    float4 a[4], b[4], c[4];
    #pragma unroll
    for (int j = 0; j < 4; j++) {
        size_t i4 = base + j * 256;
        a[j] = ((const float4*)g_rbuf)[i4];
        b[j] = ((const float4*)g_rbuf)[off1 + i4];
        c[j] = ((const float4*)g_rbuf)[2 * off1 + i4];
    }
    #pragma unroll
    for (int j = 0; j < 4; j++) {
        size_t i4 = base + j * 256;
        int t = (int)(i4 >> 8);
        float w0 = g_top_w[2 * t], w1 = g_top_w[2 * t + 1];
        float4 o;
        o.x = c[j].x + w0 * a[j].x + w1 * b[j].x;
        o.y = c[j].y + w0 * a[j].y + w1 * b[j].y;
        o.z = c[j].z + w0 * a[j].z + w1 * b[j].z;
        o.w = c[j].w + w0 * a[j].w + w1 * b[j].w;
        ((float4*)out)[i4] = o;
    }
}

// ---------------- launch ----------------------------------------------------
extern "C" void kernel_launch(void* const* d_in, const int* in_sizes, int n_in,
                              void* d_out, int out_size)
{
    const float* x  = (const float*)d_in[0];
    const float* sg = (const float*)d_in[1];
    const float* su = (const float*)d_in[2];
    const float* sd = (const float*)d_in[3];
    const float* Wg = (const float*)d_in[4];
    const float* Wu = (const float*)d_in[5];
    const float* Wd = (const float*)d_in[6];
    const float* Wr = (const float*)d_in[7];
    const float* lt = (const float*)d_in[8];
    const int*   li = (const int*)d_in[9];
    float* out = (float*)d_out;
    (void)in_sizes; (void)n_in; (void)out_size;

    static cudaStream_t s2 = nullptr;
    static cudaEvent_t evFork = nullptr, evGU = nullptr, evD = nullptr;
    static int init_done = 0;
    if (!init_done) {
        cudaFuncSetAttribute(gemm1_kernel, cudaFuncAttributeMaxDynamicSharedMemorySize, 3 * S1_STG);
        cudaFuncSetAttribute(gemm2_kernel, cudaFuncAttributeMaxDynamicSharedMemorySize, 3 * S2_STG);
        cudaStreamCreateWithFlags(&s2, cudaStreamNonBlocking);
        cudaEventCreateWithFlags(&evFork, cudaEventDisableTiming);
        cudaEventCreateWithFlags(&evGU, cudaEventDisableTiming);
        cudaEventCreateWithFlags(&evD, cudaEventDisableTiming);
        init_done = 1;
    }

    cudaEventRecord(evFork, 0);
    cudaStreamWaitEvent(s2, evFork, 0);

    zero_kernel<<<1, 32>>>();
    router_kernel<<<N_TOK / 8, 256>>>(x, Wr, lt, li);   // fused convert_x + dispatch

    convert_w_gu_kernel<<<dim3((DIM * HID / 4) / 1024, 18), 256, 0, s2>>>(Wg, Wu, sg, su);
    cudaEventRecord(evGU, s2);
    convert_w_d_kernel<<<dim3((DIM * HID / 4) / 1024, 9), 256, 0, s2>>>(Wd, sd);
    cudaEventRecord(evD, s2);

    cudaStreamWaitEvent(0, evGU, 0);
    gemm1_kernel<<<dim3(16, 32, NSEG), 256, 3 * S1_STG>>>();
    cudaStreamWaitEvent(0, evD, 0);
    gemm2_kernel<<<dim3(16, 32, NSEG), 256, 3 * S2_STG>>>();
    combine_kernel<<<(N_TOK * (DIM / 4)) / 1024, 256>>>(out);
}